// round 8
// baseline (speedup 1.0000x reference)
#include <cuda_runtime.h>
#include <math.h>

#define BB   32
#define LL   2048
#define HH   512
#define H2   1024
#define VV   32000
#define NB   592                // 4 x 148, all co-resident at occ 4
#define NSM  148
#define GSM  51                 // SMs dedicated to GEMV
#define NGB  (GSM * 4)          // 204 GEMV blocks
#define NRB  ((NSM - GSM) * 4)  // 388 reduction blocks
#define NWG  (NGB * 8)          // 1632 GEMV warps

// ---- scratch ----
__device__ float g_part31[NB][H2];          // 2.4 MB
__device__ float g_c31[H2];
__device__ float g_v[H2];
__device__ float g_partial2[31][32][H2];    // 4 MB
__device__ float g_cT[H2][BB];
__device__ float g_hT[2][HH][BB];
__device__ float g_logits[VV];
__device__ float g_pm[NWG];
__device__ float g_ps[NWG];
__device__ float g_logZ;
__device__ int   g_vready;

// ---- self-resetting sense-reversal barriers ----
__device__ volatile unsigned g_genA = 0;  __device__ unsigned g_cntA = 0;  // all 592
__device__ volatile unsigned g_genP = 0;  __device__ unsigned g_cntP = 0;  // bid<148

__device__ __forceinline__ void barrier_n(volatile unsigned* gen, unsigned* cnt, unsigned n) {
    __syncthreads();
    if (threadIdx.x == 0) {
        unsigned g = *gen;
        __threadfence();
        if (atomicAdd(cnt, 1u) == n - 1) {
            *cnt = 0;
            __threadfence();
            *gen = g + 1;
        } else {
            while (*gen == g) { }
        }
        __threadfence();
    }
    __syncthreads();
}

__device__ __forceinline__ void f4acc(float4& a, const float4 v) {
    a.x += v.x; a.y += v.y; a.z += v.z; a.w += v.w;
}

__device__ __forceinline__ void lse_merge(float& m, float& s, float m2, float s2) {
    if (m2 == -INFINITY) return;
    float M = fmaxf(m, m2);
    s = s * expf(m - M) + s2 * expf(m2 - M);
    m = M;
}

__global__ void init_kernel() { g_vready = 0; }

__global__ void __launch_bounds__(256, 4) fused_decoder(
        const float* __restrict__ h,    const float* __restrict__ enc,
        const float* __restrict__ Wihf, const float* __restrict__ Whhf,
        const float* __restrict__ bihf, const float* __restrict__ bhhf,
        const float* __restrict__ Wihb, const float* __restrict__ Whhb,
        const float* __restrict__ bihb, const float* __restrict__ bhhb,
        const float* __restrict__ outW, const float* __restrict__ outb,
        float* __restrict__ out) {
    __shared__ float sv[H2];
    __shared__ float sp[4][4][32];
    const int bid = blockIdx.x, tid = threadIdx.x;
    const int lane = tid & 31, w = tid >> 5;
    const int sm_res = bid % NSM, wave = bid / NSM;
    const bool is_gemv = sm_res < GSM;

    // ========== P0 (all blocks): reduce encoder_out[b=31] (8 MB) ===========
    {
        const float4* e4 = (const float4*)enc + (size_t)31 * LL * 256;
        float4 a = make_float4(0.f, 0.f, 0.f, 0.f);
        for (int row = bid; row < LL; row += NB)
            f4acc(a, __ldcs(&e4[(size_t)row * 256 + tid]));
        ((float4*)g_part31[bid])[tid] = a;
    }
    barrier_n(&g_genA, &g_cntA, NB);

    // ========== Prologue continues on bid<148 (one block per SM) ===========
    if (bid < NSM) {
        if (bid < 4) {        // finalize c31
            int col = bid * 256 + tid;
            float s = 0.f;
            #pragma unroll 8
            for (int p = 0; p < NB; p++) s += g_part31[p][col];
            s *= (1.0f / (float)LL);
            g_c31[col] = s < 0.f ? 0.f : s;
        }
        barrier_n(&g_genP, &g_cntP, NSM);
        {   // GRU for batch 31 -> g_v; 1024 of 1184 warps, spread on all SMs
            int gw = bid * 8 + w;
            if (gw < 1024) {
                int dir = gw >> 9, u = gw & (HH - 1);
                const float* Wih = dir ? Wihb : Wihf;
                const float* Whh = dir ? Whhb : Whhf;
                const float* bih = dir ? bihb : bihf;
                const float* bhh = dir ? bhhb : bhhf;
                const float4* c4 = (const float4*)g_c31;
                const float4* h4 = (const float4*)(h + dir * BB * HH + 31 * HH);
                float gr = 0.f, gz = 0.f, gin = 0.f, ghn = 0.f;
                const float4* Wr = (const float4*)(Wih + (size_t)u * H2);
                const float4* Wz = (const float4*)(Wih + (size_t)(HH + u) * H2);
                const float4* Wn = (const float4*)(Wih + (size_t)(2 * HH + u) * H2);
                #pragma unroll
                for (int i = 0; i < 8; i++) {
                    int k4 = i * 32 + lane;
                    float4 c = c4[k4];
                    float4 wr = __ldg(Wr + k4), wz = __ldg(Wz + k4), wn = __ldg(Wn + k4);
                    gr  += c.x * wr.x + c.y * wr.y + c.z * wr.z + c.w * wr.w;
                    gz  += c.x * wz.x + c.y * wz.y + c.z * wz.z + c.w * wz.w;
                    gin += c.x * wn.x + c.y * wn.y + c.z * wn.z + c.w * wn.w;
                }
                const float4* Vr = (const float4*)(Whh + (size_t)u * HH);
                const float4* Vz = (const float4*)(Whh + (size_t)(HH + u) * HH);
                const float4* Vn = (const float4*)(Whh + (size_t)(2 * HH + u) * HH);
                #pragma unroll
                for (int i = 0; i < 4; i++) {
                    int k4 = i * 32 + lane;
                    float4 hv = __ldg(h4 + k4);
                    float4 vr = __ldg(Vr + k4), vz = __ldg(Vz + k4), vn = __ldg(Vn + k4);
                    gr  += hv.x * vr.x + hv.y * vr.y + hv.z * vr.z + hv.w * vr.w;
                    gz  += hv.x * vz.x + hv.y * vz.y + hv.z * vz.z + hv.w * vz.w;
                    ghn += hv.x * vn.x + hv.y * vn.y + hv.z * vn.z + hv.w * vn.w;
                }
                #pragma unroll
                for (int o = 16; o; o >>= 1) {
                    gr  += __shfl_down_sync(0xFFFFFFFFu, gr, o);
                    gz  += __shfl_down_sync(0xFFFFFFFFu, gz, o);
                    gin += __shfl_down_sync(0xFFFFFFFFu, gin, o);
                    ghn += __shfl_down_sync(0xFFFFFFFFu, ghn, o);
                }
                if (lane == 0) {
                    gr  += bih[u] + bhh[u];
                    gz  += bih[HH + u] + bhh[HH + u];
                    gin += bih[2 * HH + u];
                    ghn += bhh[2 * HH + u];
                    float r = 1.f / (1.f + expf(-gr));
                    float z = 1.f / (1.f + expf(-gz));
                    float n = tanhf(gin + r * ghn);
                    float hold = h[dir * BB * HH + 31 * HH + u];
                    g_v[dir * HH + u] = (1.f - z) * n + z * hold;
                }
            }
        }
        barrier_n(&g_genP, &g_cntP, NSM);
        if (bid == 0 && tid == 0) {
            __threadfence();
            g_vready = 1;
        }
    } else if (is_gemv) {
        // GEMV blocks not in prologue group: wait for v
        if (tid == 0) {
            while (*(volatile int*)&g_vready == 0) { }
        }
        __syncthreads();
        __threadfence_block();
    }

    // ========== STREAMS: SM-partitioned ====================================
    if (is_gemv) {
        // ---- 51 SMs x 4 blocks: vocab GEMV (131 MB) + softmax partials ----
        for (int i = tid; i < H2; i += 256) sv[i] = g_v[i];
        __syncthreads();
        int gi = wave * GSM + sm_res;        // 0..203
        int gw = gi * 8 + w;                 // 0..1631
        const float4* vp = (const float4*)sv;
        float m = -INFINITY, s = 0.f;
        for (int r = gw; r < VV; r += NWG) {
            const float4* wp = (const float4*)(outW + (size_t)r * H2);
            float acc = 0.f;
            #pragma unroll
            for (int i = 0; i < 8; i++) {
                float4 a = __ldcs(wp + i * 32 + lane);
                float4 v = vp[i * 32 + lane];
                acc += a.x * v.x + a.y * v.y + a.z * v.z + a.w * v.w;
            }
            #pragma unroll
            for (int o = 16; o; o >>= 1) acc += __shfl_xor_sync(0xFFFFFFFFu, acc, o);
            float lg = acc + __ldg(outb + r);
            if (lane == 0) g_logits[r] = lg;
            float M = fmaxf(m, lg);
            s = s * expf(m - M) + expf(lg - M);
            m = M;
        }
        if (lane == 0) { g_pm[gw] = m; g_ps[gw] = s; }
    } else {
        // ---- 97 SMs x 4 blocks: stream batches 0..30 (248 MB) -------------
        int ri = wave * (NSM - GSM) + (sm_res - GSM);   // 0..387
        for (int c = ri; c < 31 * 32; c += NRB) {
            int b = c >> 5, ch = c & 31;
            const float4* p = (const float4*)enc + ((size_t)b * LL + ch * 64) * 256;
            float4 a0 = make_float4(0.f, 0.f, 0.f, 0.f), a1 = a0, a2 = a0, a3 = a0;
            #pragma unroll 1
            for (int l = 0; l < 64; l += 8) {
                float4 v0 = __ldcs(&p[(size_t)(l + 0) * 256 + tid]);
                float4 v1 = __ldcs(&p[(size_t)(l + 1) * 256 + tid]);
                float4 v2 = __ldcs(&p[(size_t)(l + 2) * 256 + tid]);
                float4 v3 = __ldcs(&p[(size_t)(l + 3) * 256 + tid]);
                float4 v4 = __ldcs(&p[(size_t)(l + 4) * 256 + tid]);
                float4 v5 = __ldcs(&p[(size_t)(l + 5) * 256 + tid]);
                float4 v6 = __ldcs(&p[(size_t)(l + 6) * 256 + tid]);
                float4 v7 = __ldcs(&p[(size_t)(l + 7) * 256 + tid]);
                f4acc(a0, v0); f4acc(a0, v4);
                f4acc(a1, v1); f4acc(a1, v5);
                f4acc(a2, v2); f4acc(a2, v6);
                f4acc(a3, v3); f4acc(a3, v7);
            }
            float4 s4;
            s4.x = (a0.x + a1.x) + (a2.x + a3.x);
            s4.y = (a0.y + a1.y) + (a2.y + a3.y);
            s4.z = (a0.z + a1.z) + (a2.z + a3.z);
            s4.w = (a0.w + a1.w) + (a2.w + a3.w);
            ((float4*)g_partial2[b][ch])[tid] = s4;
        }
    }
    barrier_n(&g_genA, &g_cntA, NB);

    // ========== EPILOGUE A: cT / hT / attn fill / logZ =====================
    {
        int idx = bid * 256 + tid;
        if (idx < BB * H2) {
            int b = idx >> 10, col = idx & (H2 - 1);
            float s;
            if (b < 31) {
                s = 0.f;
                #pragma unroll 8
                for (int ch = 0; ch < 32; ch++) s += g_partial2[b][ch][col];
                s *= (1.0f / (float)LL);
                if (s < 0.f) s = 0.f;
            } else {
                s = g_c31[col];
            }
            g_cT[col][b] = s;
        } else if (idx < 2 * BB * H2) {
            int j = idx - BB * H2;
            int dir = j >> 14, bb2 = (j >> 9) & 31, u = j & (HH - 1);
            g_hT[dir][u][bb2] = h[j];
            out[VV + 2 * BB * HH + (idx - BB * H2)] = 1.0f / (float)LL;
            out[VV + 2 * BB * HH + idx] = 1.0f / (float)LL;
        }
        if (bid == NB - 1 && w == 0) {
            float m = -INFINITY, s = 0.f;
            for (int i = lane; i < NWG; i += 32)
                lse_merge(m, s, g_pm[i], g_ps[i]);
            #pragma unroll
            for (int o = 16; o; o >>= 1) {
                float m2 = __shfl_xor_sync(0xFFFFFFFFu, m, o);
                float s2 = __shfl_xor_sync(0xFFFFFFFFu, s, o);
                lse_merge(m, s, m2, s2);
            }
            if (lane == 0) g_logZ = m + logf(s);
        }
    }
    barrier_n(&g_genA, &g_cntA, NB);

    // ========== EPILOGUE B: full GRU (K-split x2) + logp write =============
    if (bid < 256) {
        int p    = bid * 4 + (w & 3);
        int half = w >> 2;
        int dir  = p >> 9, u = p & (HH - 1);
        const float* Wih = dir ? Wihb : Wihf;
        const float* Whh = dir ? Whhb : Whhf;
        const float* bih = dir ? bihb : bihf;
        const float* bhh = dir ? bhhb : bhhf;
        float gr = 0.f, gz = 0.f, gin = 0.f, ghn = 0.f;
        {
            const float4* Wr = (const float4*)(Wih + (size_t)u * H2) + half * 128;
            const float4* Wz = (const float4*)(Wih + (size_t)(HH + u) * H2) + half * 128;
            const float4* Wn = (const float4*)(Wih + (size_t)(2 * HH + u) * H2) + half * 128;
            int kb = half * 512;
            #pragma unroll 4
            for (int k4 = 0; k4 < 128; k4++) {
                float c0 = g_cT[kb + k4 * 4 + 0][lane];
                float c1 = g_cT[kb + k4 * 4 + 1][lane];
                float c2 = g_cT[kb + k4 * 4 + 2][lane];
                float c3 = g_cT[kb + k4 * 4 + 3][lane];
                float4 wr = __ldg(Wr + k4), wz = __ldg(Wz + k4), wn = __ldg(Wn + k4);
                gr  += c0 * wr.x + c1 * wr.y + c2 * wr.z + c3 * wr.w;
                gz  += c0 * wz.x + c1 * wz.y + c2 * wz.z + c3 * wz.w;
                gin += c0 * wn.x + c1 * wn.y + c2 * wn.z + c3 * wn.w;
            }
        }
        {
            const float4* Vr = (const float4*)(Whh + (size_t)u * HH) + half * 64;
            const float4* Vz = (const float4*)(Whh + (size_t)(HH + u) * HH) + half * 64;
            const float4* Vn = (const float4*)(Whh + (size_t)(2 * HH + u) * HH) + half * 64;
            int kb = half * 256;
            #pragma unroll 4
            for (int k4 = 0; k4 < 64; k4++) {
                float h0 = g_hT[dir][kb + k4 * 4 + 0][lane];
                float h1 = g_hT[dir][kb + k4 * 4 + 1][lane];
                float h2 = g_hT[dir][kb + k4 * 4 + 2][lane];
                float h3 = g_hT[dir][kb + k4 * 4 + 3][lane];
                float4 vr = __ldg(Vr + k4), vz = __ldg(Vz + k4), vn = __ldg(Vn + k4);
                gr  += h0 * vr.x + h1 * vr.y + h2 * vr.z + h3 * vr.w;
                gz  += h0 * vz.x + h1 * vz.y + h2 * vz.z + h3 * vz.w;
                ghn += h0 * vn.x + h1 * vn.y + h2 * vn.z + h3 * vn.w;
            }
        }
        if (half) {
            sp[w & 3][0][lane] = gr;
            sp[w & 3][1][lane] = gz;
            sp[w & 3][2][lane] = gin;
            sp[w & 3][3][lane] = ghn;
        }
        __syncthreads();
        if (!half) {
            gr  += sp[w & 3][0][lane] + bih[u] + bhh[u];
            gz  += sp[w & 3][1][lane] + bih[HH + u] + bhh[HH + u];
            gin += sp[w & 3][2][lane] + bih[2 * HH + u];
            ghn += sp[w & 3][3][lane] + bhh[2 * HH + u];
            float r = 1.f / (1.f + expf(-gr));
            float z = 1.f / (1.f + expf(-gz));
            float n = tanhf(gin + r * ghn);
            float hold = h[dir * BB * HH + lane * HH + u];
            out[VV + dir * BB * HH + lane * HH + u] = (1.f - z) * n + z * hold;
        }
    } else if (bid < 381) {
        int idx = (bid - 256) * 256 + tid;
        if (idx < VV) out[idx] = __ldg(&g_logits[idx]) - g_logZ;
    }
}

extern "C" void kernel_launch(void* const* d_in, const int* in_sizes, int n_in,
                              void* d_out, int out_size) {
    const float* h    = (const float*)d_in[1];
    const float* enc  = (const float*)d_in[2];
    const float* Wihf = (const float*)d_in[6];
    const float* Whhf = (const float*)d_in[7];
    const float* bihf = (const float*)d_in[8];
    const float* bhhf = (const float*)d_in[9];
    const float* Wihb = (const float*)d_in[10];
    const float* Whhb = (const float*)d_in[11];
    const float* bihb = (const float*)d_in[12];
    const float* bhhb = (const float*)d_in[13];
    const float* outW = (const float*)d_in[14];
    const float* outb = (const float*)d_in[15];
    float* out = (float*)d_out;

    init_kernel<<<1, 1>>>();
    fused_decoder<<<NB, 256>>>(h, enc, Wihf, Whhf, bihf, bhhf,
                               Wihb, Whhb, bihb, bhhb, outW, outb, out);
}

// round 9
// speedup vs baseline: 1.1336x; 1.1336x over previous
#include <cuda_runtime.h>
#include <math.h>

#define BB   32
#define LL   2048
#define HH   512
#define H2   1024
#define VV   32000

// ---- scratch ----
__device__ float g_part1[512][H2];          // 2 MB block partials (16 per batch)
__device__ float g_cT[H2][BB];              // relu(mean) context, transposed
__device__ float g_hT[2][HH][BB];           // h transposed
__device__ float g_logits[VV];
__device__ float g_pm[1024];
__device__ float g_ps[1024];

// ======= K1: enc reduction, GEMV-shaped (warp = 32 contiguous rows) ========
__global__ void __launch_bounds__(128) k1_reduce(const float* __restrict__ enc) {
    __shared__ float red[4][H2];
    int b  = blockIdx.x >> 4;            // batch 0..31
    int ch = blockIdx.x & 15;            // 128-row chunk within batch
    int w  = threadIdx.x >> 5, lane = threadIdx.x & 31;
    // warp w: rows [ch*128 + w*32, +32) -> 128 KB contiguous
    const float4* base = (const float4*)enc +
        ((size_t)b * LL + ch * 128 + w * 32) * 256;
    float4 a0 = make_float4(0.f,0.f,0.f,0.f), a1=a0, a2=a0, a3=a0, a4=a0, a5=a0, a6=a0, a7=a0;
    #pragma unroll 1
    for (int r = 0; r < 32; r++) {
        const float4* row = base + (size_t)r * 256;
        float4 v0 = row[0 * 32 + lane];
        float4 v1 = row[1 * 32 + lane];
        float4 v2 = row[2 * 32 + lane];
        float4 v3 = row[3 * 32 + lane];
        float4 v4 = row[4 * 32 + lane];
        float4 v5 = row[5 * 32 + lane];
        float4 v6 = row[6 * 32 + lane];
        float4 v7 = row[7 * 32 + lane];
        a0.x += v0.x; a0.y += v0.y; a0.z += v0.z; a0.w += v0.w;
        a1.x += v1.x; a1.y += v1.y; a1.z += v1.z; a1.w += v1.w;
        a2.x += v2.x; a2.y += v2.y; a2.z += v2.z; a2.w += v2.w;
        a3.x += v3.x; a3.y += v3.y; a3.z += v3.z; a3.w += v3.w;
        a4.x += v4.x; a4.y += v4.y; a4.z += v4.z; a4.w += v4.w;
        a5.x += v5.x; a5.y += v5.y; a5.z += v5.z; a5.w += v5.w;
        a6.x += v6.x; a6.y += v6.y; a6.z += v6.z; a6.w += v6.w;
        a7.x += v7.x; a7.y += v7.y; a7.z += v7.z; a7.w += v7.w;
    }
    float4* rw = (float4*)red[w];
    rw[0 * 32 + lane] = a0;  rw[1 * 32 + lane] = a1;
    rw[2 * 32 + lane] = a2;  rw[3 * 32 + lane] = a3;
    rw[4 * 32 + lane] = a4;  rw[5 * 32 + lane] = a5;
    rw[6 * 32 + lane] = a6;  rw[7 * 32 + lane] = a7;
    __syncthreads();
    // combine 4 warps -> one 1024-float partial per block (2 float4/thread)
    #pragma unroll
    for (int i = 0; i < 2; i++) {
        int t = threadIdx.x + i * 128;
        float4 s = ((float4*)red[0])[t];
        float4 x1 = ((float4*)red[1])[t];
        float4 x2 = ((float4*)red[2])[t];
        float4 x3 = ((float4*)red[3])[t];
        s.x += x1.x + x2.x + x3.x;
        s.y += x1.y + x2.y + x3.y;
        s.z += x1.z + x2.z + x3.z;
        s.w += x1.w + x2.w + x3.w;
        ((float4*)g_part1[blockIdx.x])[t] = s;
    }
}

// ======= K1b: finalize c (relu/mean, transposed), transpose h, attn fill ===
__global__ void k1b_finalize(const float* __restrict__ h, float* __restrict__ out) {
    int idx = blockIdx.x * 256 + threadIdx.x;      // 0..65535
    out[VV + 2 * BB * HH + idx] = 1.0f / (float)LL;
    if (idx < BB * H2) {
        int b = idx >> 10, col = idx & (H2 - 1);
        float s = 0.f;
        #pragma unroll
        for (int ch = 0; ch < 16; ch++) s += g_part1[b * 16 + ch][col];
        s *= (1.0f / (float)LL);
        if (s < 0.f) s = 0.f;
        g_cT[col][b] = s;
        int dir = idx >> 14, bb = (idx >> 9) & 31, u = idx & (HH - 1);
        g_hT[dir][u][bb] = h[idx];
    }
}

// ======= K2: fused GRU, K-split x4 (4 warps per (dir,u)) ===================
__global__ void __launch_bounds__(128) k2_gru(
        const float* __restrict__ h,
        const float* __restrict__ Wihf, const float* __restrict__ Whhf,
        const float* __restrict__ bihf, const float* __restrict__ bhhf,
        const float* __restrict__ Wihb, const float* __restrict__ Whhb,
        const float* __restrict__ bihb, const float* __restrict__ bhhb,
        float* __restrict__ out) {
    __shared__ float sp[3][4][32];
    int lane = threadIdx.x & 31;
    int w    = threadIdx.x >> 5;         // quarter 0..3
    int p    = blockIdx.x;               // 0..1023
    int dir  = p >> 9, u = p & (HH - 1);
    const float* Wih = dir ? Wihb : Wihf;
    const float* Whh = dir ? Whhb : Whhf;
    const float* bih = dir ? bihb : bihf;
    const float* bhh = dir ? bhhb : bhhf;

    float gr = 0.f, gz = 0.f, gin = 0.f, ghn = 0.f;
    {   // input-hidden quarter: cols [w*256, w*256+256)
        const float4* Wr = (const float4*)(Wih + (size_t)u * H2) + w * 64;
        const float4* Wz = (const float4*)(Wih + (size_t)(HH + u) * H2) + w * 64;
        const float4* Wn = (const float4*)(Wih + (size_t)(2 * HH + u) * H2) + w * 64;
        int kb = w * 256;
        #pragma unroll 8
        for (int k4 = 0; k4 < 64; k4++) {
            float c0 = g_cT[kb + k4 * 4 + 0][lane];
            float c1 = g_cT[kb + k4 * 4 + 1][lane];
            float c2 = g_cT[kb + k4 * 4 + 2][lane];
            float c3 = g_cT[kb + k4 * 4 + 3][lane];
            float4 wr = Wr[k4], wz = Wz[k4], wn = Wn[k4];
            gr  += c0 * wr.x + c1 * wr.y + c2 * wr.z + c3 * wr.w;
            gz  += c0 * wz.x + c1 * wz.y + c2 * wz.z + c3 * wz.w;
            gin += c0 * wn.x + c1 * wn.y + c2 * wn.z + c3 * wn.w;
        }
    }
    {   // hidden-hidden quarter: cols [w*128, w*128+128)
        const float4* Vr = (const float4*)(Whh + (size_t)u * HH) + w * 32;
        const float4* Vz = (const float4*)(Whh + (size_t)(HH + u) * HH) + w * 32;
        const float4* Vn = (const float4*)(Whh + (size_t)(2 * HH + u) * HH) + w * 32;
        int kb = w * 128;
        #pragma unroll 8
        for (int k4 = 0; k4 < 32; k4++) {
            float h0 = g_hT[dir][kb + k4 * 4 + 0][lane];
            float h1 = g_hT[dir][kb + k4 * 4 + 1][lane];
            float h2 = g_hT[dir][kb + k4 * 4 + 2][lane];
            float h3 = g_hT[dir][kb + k4 * 4 + 3][lane];
            float4 vr = Vr[k4], vz = Vz[k4], vn = Vn[k4];
            gr  += h0 * vr.x + h1 * vr.y + h2 * vr.z + h3 * vr.w;
            gz  += h0 * vz.x + h1 * vz.y + h2 * vz.z + h3 * vz.w;
            ghn += h0 * vn.x + h1 * vn.y + h2 * vn.z + h3 * vn.w;
        }
    }
    if (w) {
        sp[w - 1][0][lane] = gr;
        sp[w - 1][1][lane] = gz;
        sp[w - 1][2][lane] = gin;
        sp[w - 1][3][lane] = ghn;
    }
    __syncthreads();
    if (w == 0) {
        #pragma unroll
        for (int q = 0; q < 3; q++) {
            gr  += sp[q][0][lane];
            gz  += sp[q][1][lane];
            gin += sp[q][2][lane];
            ghn += sp[q][3][lane];
        }
        gr  += bih[u] + bhh[u];
        gz  += bih[HH + u] + bhh[HH + u];
        gin += bih[2 * HH + u];
        ghn += bhh[2 * HH + u];
        float r = 1.f / (1.f + expf(-gr));
        float z = 1.f / (1.f + expf(-gz));
        float n = tanhf(gin + r * ghn);
        float hold = h[dir * BB * HH + lane * HH + u];
        out[VV + dir * BB * HH + lane * HH + u] = (1.f - z) * n + z * hold;
    }
}

// ======= K3a: logits GEMV (exact R1 shape: 26.5us @ 5.1 TB/s) ==============
__global__ void k3a_logits(const float* __restrict__ outW,
                           const float* __restrict__ outb,
                           const float* __restrict__ dout) {
    __shared__ float sv[H2];
    __shared__ float rl[32];
    int tid = threadIdx.x, lane = tid & 31, w = tid >> 5;
    for (int i = tid; i < H2; i += 256) {
        int dir = i >> 9, uu = i & (HH - 1);
        sv[i] = dout[VV + dir * BB * HH + 31 * HH + uu];
    }
    __syncthreads();
    int r0 = blockIdx.x * 32 + w * 4;
    const float4* vp = (const float4*)sv;
    #pragma unroll 1
    for (int ri = 0; ri < 4; ri++) {
        int r = r0 + ri;
        const float4* wp = (const float4*)(outW + (size_t)r * H2);
        float acc = 0.f;
        #pragma unroll
        for (int i = 0; i < 8; i++) {
            float4 a = wp[i * 32 + lane];
            float4 v = vp[i * 32 + lane];
            acc += a.x * v.x + a.y * v.y + a.z * v.z + a.w * v.w;
        }
        #pragma unroll
        for (int o = 16; o; o >>= 1) acc += __shfl_down_sync(0xFFFFFFFFu, acc, o);
        if (lane == 0) {
            float lg = acc + outb[r];
            g_logits[r] = lg;
            rl[w * 4 + ri] = lg;
        }
    }
    __syncthreads();
    if (w == 0) {
        float x = rl[lane];
        float m = x;
        #pragma unroll
        for (int o = 16; o; o >>= 1) m = fmaxf(m, __shfl_xor_sync(0xFFFFFFFFu, m, o));
        float s = expf(x - m);
        #pragma unroll
        for (int o = 16; o; o >>= 1) s += __shfl_xor_sync(0xFFFFFFFFu, s, o);
        if (lane == 0) { g_pm[blockIdx.x] = m; g_ps[blockIdx.x] = s; }
    }
}

// ======= K3c: merge partials (L2-hot) -> write logp ========================
__global__ void k3c_logp(float* __restrict__ out) {
    const int NBK = 1000;
    int tid = threadIdx.x, lane = tid & 31;
    float m = g_pm[tid], s = g_ps[tid];
    for (int i = tid + 256; i < NBK; i += 256) {
        float m2 = g_pm[i], s2 = g_ps[i];
        float M = fmaxf(m, m2);
        s = s * expf(m - M) + s2 * expf(m2 - M);
        m = M;
    }
    #pragma unroll
    for (int o = 16; o; o >>= 1) {
        float m2 = __shfl_xor_sync(0xFFFFFFFFu, m, o);
        float s2 = __shfl_xor_sync(0xFFFFFFFFu, s, o);
        float M = fmaxf(m, m2);
        s = s * expf(m - M) + s2 * expf(m2 - M);
        m = M;
    }
    __shared__ float sm[8], ss[8];
    __shared__ float s_logZ;
    if (lane == 0) { sm[tid >> 5] = m; ss[tid >> 5] = s; }
    __syncthreads();
    if (tid == 0) {
        float M = sm[0], S = ss[0];
        #pragma unroll
        for (int i = 1; i < 8; i++) {
            float M2 = fmaxf(M, sm[i]);
            S = S * expf(M - M2) + ss[i] * expf(sm[i] - M2);
            M = M2;
        }
        s_logZ = M + logf(S);
    }
    __syncthreads();
    int idx = blockIdx.x * 256 + tid;
    out[idx] = g_logits[idx] - s_logZ;
}

extern "C" void kernel_launch(void* const* d_in, const int* in_sizes, int n_in,
                              void* d_out, int out_size) {
    const float* h    = (const float*)d_in[1];
    const float* enc  = (const float*)d_in[2];
    const float* Wihf = (const float*)d_in[6];
    const float* Whhf = (const float*)d_in[7];
    const float* bihf = (const float*)d_in[8];
    const float* bhhf = (const float*)d_in[9];
    const float* Wihb = (const float*)d_in[10];
    const float* Whhb = (const float*)d_in[11];
    const float* bihb = (const float*)d_in[12];
    const float* bhhb = (const float*)d_in[13];
    const float* outW = (const float*)d_in[14];
    const float* outb = (const float*)d_in[15];
    float* out = (float*)d_out;

    k1_reduce<<<512, 128>>>(enc);                          // 256 MB stream
    k1b_finalize<<<256, 256>>>(h, out);                    // c, hT, attn fill
    k2_gru<<<1024, 128>>>(h, Wihf, Whhf, bihf, bhhf,
                          Wihb, Whhb, bihb, bhhb, out);    // h_new
    k3a_logits<<<1000, 256>>>(outW, outb, out);            // logits + partials
    k3c_logp<<<125, 256>>>(out);                           // logp
}

// round 10
// speedup vs baseline: 1.1679x; 1.0303x over previous
#include <cuda_runtime.h>
#include <math.h>

#define BB   32
#define LL   2048
#define HH   512
#define H2   1024
#define VV   32000

// ---- scratch ----
__device__ float g_part1[1024][H2];         // 4 MB block partials (32 per batch)
__device__ float g_cT[H2][BB];              // relu(mean) context, transposed
__device__ float g_hT[2][HH][BB];           // h transposed
__device__ float g_logits[VV];
__device__ float g_pm[1024];
__device__ float g_ps[1024];

// ======= K1: enc reduction, k3a-class oversubscription =====================
// 1024 blocks x 256 thr (8192 warps). Warp = 8 contiguous rows (32 KB),
// 8 independent float4 accumulators -> 8 loads in flight per warp.
__global__ void __launch_bounds__(256) k1_reduce(const float* __restrict__ enc) {
    __shared__ float4 red[8][256];       // 32 KB: [warp][float4-column]
    int b  = blockIdx.x >> 5;            // batch 0..31
    int ch = blockIdx.x & 31;            // 64-row chunk within batch
    int w  = threadIdx.x >> 5, lane = threadIdx.x & 31;
    int tid = threadIdx.x;
    const float4* base = (const float4*)enc +
        ((size_t)b * LL + ch * 64 + w * 8) * 256;
    float4 a0 = make_float4(0.f,0.f,0.f,0.f), a1=a0, a2=a0, a3=a0, a4=a0, a5=a0, a6=a0, a7=a0;
    #pragma unroll 1
    for (int r = 0; r < 8; r++) {
        const float4* row = base + (size_t)r * 256;
        float4 v0 = row[0 * 32 + lane];
        float4 v1 = row[1 * 32 + lane];
        float4 v2 = row[2 * 32 + lane];
        float4 v3 = row[3 * 32 + lane];
        float4 v4 = row[4 * 32 + lane];
        float4 v5 = row[5 * 32 + lane];
        float4 v6 = row[6 * 32 + lane];
        float4 v7 = row[7 * 32 + lane];
        a0.x += v0.x; a0.y += v0.y; a0.z += v0.z; a0.w += v0.w;
        a1.x += v1.x; a1.y += v1.y; a1.z += v1.z; a1.w += v1.w;
        a2.x += v2.x; a2.y += v2.y; a2.z += v2.z; a2.w += v2.w;
        a3.x += v3.x; a3.y += v3.y; a3.z += v3.z; a3.w += v3.w;
        a4.x += v4.x; a4.y += v4.y; a4.z += v4.z; a4.w += v4.w;
        a5.x += v5.x; a5.y += v5.y; a5.z += v5.z; a5.w += v5.w;
        a6.x += v6.x; a6.y += v6.y; a6.z += v6.z; a6.w += v6.w;
        a7.x += v7.x; a7.y += v7.y; a7.z += v7.z; a7.w += v7.w;
    }
    red[w][0 * 32 + lane] = a0;  red[w][1 * 32 + lane] = a1;
    red[w][2 * 32 + lane] = a2;  red[w][3 * 32 + lane] = a3;
    red[w][4 * 32 + lane] = a4;  red[w][5 * 32 + lane] = a5;
    red[w][6 * 32 + lane] = a6;  red[w][7 * 32 + lane] = a7;
    __syncthreads();
    // combine 8 warps -> one 1024-float partial (1 float4 per thread)
    float4 s = red[0][tid];
    #pragma unroll
    for (int w2 = 1; w2 < 8; w2++) {
        float4 x = red[w2][tid];
        s.x += x.x; s.y += x.y; s.z += x.z; s.w += x.w;
    }
    ((float4*)g_part1[blockIdx.x])[tid] = s;
}

// ======= K1b: finalize c (relu/mean, transposed), transpose h, attn fill ===
__global__ void k1b_finalize(const float* __restrict__ h, float* __restrict__ out) {
    int idx = blockIdx.x * 256 + threadIdx.x;      // 0..65535
    out[VV + 2 * BB * HH + idx] = 1.0f / (float)LL;
    if (idx < BB * H2) {
        int b = idx >> 10, col = idx & (H2 - 1);
        float s = 0.f;
        #pragma unroll 8
        for (int ch = 0; ch < 32; ch++) s += g_part1[b * 32 + ch][col];
        s *= (1.0f / (float)LL);
        if (s < 0.f) s = 0.f;
        g_cT[col][b] = s;
        int dir = idx >> 14, bb = (idx >> 9) & 31, u = idx & (HH - 1);
        g_hT[dir][u][bb] = h[idx];
    }
}

// ======= K2: fused GRU, K-split x4 (4 warps per (dir,u)) ===================
__global__ void __launch_bounds__(128) k2_gru(
        const float* __restrict__ h,
        const float* __restrict__ Wihf, const float* __restrict__ Whhf,
        const float* __restrict__ bihf, const float* __restrict__ bhhf,
        const float* __restrict__ Wihb, const float* __restrict__ Whhb,
        const float* __restrict__ bihb, const float* __restrict__ bhhb,
        float* __restrict__ out) {
    __shared__ float sp[3][4][32];
    int lane = threadIdx.x & 31;
    int w    = threadIdx.x >> 5;         // quarter 0..3
    int p    = blockIdx.x;               // 0..1023
    int dir  = p >> 9, u = p & (HH - 1);
    const float* Wih = dir ? Wihb : Wihf;
    const float* Whh = dir ? Whhb : Whhf;
    const float* bih = dir ? bihb : bihf;
    const float* bhh = dir ? bhhb : bhhf;

    float gr = 0.f, gz = 0.f, gin = 0.f, ghn = 0.f;
    {   // input-hidden quarter: cols [w*256, w*256+256)
        const float4* Wr = (const float4*)(Wih + (size_t)u * H2) + w * 64;
        const float4* Wz = (const float4*)(Wih + (size_t)(HH + u) * H2) + w * 64;
        const float4* Wn = (const float4*)(Wih + (size_t)(2 * HH + u) * H2) + w * 64;
        int kb = w * 256;
        #pragma unroll 8
        for (int k4 = 0; k4 < 64; k4++) {
            float c0 = g_cT[kb + k4 * 4 + 0][lane];
            float c1 = g_cT[kb + k4 * 4 + 1][lane];
            float c2 = g_cT[kb + k4 * 4 + 2][lane];
            float c3 = g_cT[kb + k4 * 4 + 3][lane];
            float4 wr = Wr[k4], wz = Wz[k4], wn = Wn[k4];
            gr  += c0 * wr.x + c1 * wr.y + c2 * wr.z + c3 * wr.w;
            gz  += c0 * wz.x + c1 * wz.y + c2 * wz.z + c3 * wz.w;
            gin += c0 * wn.x + c1 * wn.y + c2 * wn.z + c3 * wn.w;
        }
    }
    {   // hidden-hidden quarter: cols [w*128, w*128+128)
        const float4* Vr = (const float4*)(Whh + (size_t)u * HH) + w * 32;
        const float4* Vz = (const float4*)(Whh + (size_t)(HH + u) * HH) + w * 32;
        const float4* Vn = (const float4*)(Whh + (size_t)(2 * HH + u) * HH) + w * 32;
        int kb = w * 128;
        #pragma unroll 8
        for (int k4 = 0; k4 < 32; k4++) {
            float h0 = g_hT[dir][kb + k4 * 4 + 0][lane];
            float h1 = g_hT[dir][kb + k4 * 4 + 1][lane];
            float h2 = g_hT[dir][kb + k4 * 4 + 2][lane];
            float h3 = g_hT[dir][kb + k4 * 4 + 3][lane];
            float4 vr = Vr[k4], vz = Vz[k4], vn = Vn[k4];
            gr  += h0 * vr.x + h1 * vr.y + h2 * vr.z + h3 * vr.w;
            gz  += h0 * vz.x + h1 * vz.y + h2 * vz.z + h3 * vz.w;
            ghn += h0 * vn.x + h1 * vn.y + h2 * vn.z + h3 * vn.w;
        }
    }
    if (w) {
        sp[w - 1][0][lane] = gr;
        sp[w - 1][1][lane] = gz;
        sp[w - 1][2][lane] = gin;
        sp[w - 1][3][lane] = ghn;
    }
    __syncthreads();
    if (w == 0) {
        #pragma unroll
        for (int q = 0; q < 3; q++) {
            gr  += sp[q][0][lane];
            gz  += sp[q][1][lane];
            gin += sp[q][2][lane];
            ghn += sp[q][3][lane];
        }
        gr  += bih[u] + bhh[u];
        gz  += bih[HH + u] + bhh[HH + u];
        gin += bih[2 * HH + u];
        ghn += bhh[2 * HH + u];
        float r = 1.f / (1.f + expf(-gr));
        float z = 1.f / (1.f + expf(-gz));
        float n = tanhf(gin + r * ghn);
        float hold = h[dir * BB * HH + lane * HH + u];
        out[VV + dir * BB * HH + lane * HH + u] = (1.f - z) * n + z * hold;
    }
}

// ======= K3a: logits GEMV (proven 26.8us @ 5.0 TB/s) =======================
__global__ void k3a_logits(const float* __restrict__ outW,
                           const float* __restrict__ outb,
                           const float* __restrict__ dout) {
    __shared__ float sv[H2];
    __shared__ float rl[32];
    int tid = threadIdx.x, lane = tid & 31, w = tid >> 5;
    for (int i = tid; i < H2; i += 256) {
        int dir = i >> 9, uu = i & (HH - 1);
        sv[i] = dout[VV + dir * BB * HH + 31 * HH + uu];
    }
    __syncthreads();
    int r0 = blockIdx.x * 32 + w * 4;
    const float4* vp = (const float4*)sv;
    #pragma unroll 1
    for (int ri = 0; ri < 4; ri++) {
        int r = r0 + ri;
        const float4* wp = (const float4*)(outW + (size_t)r * H2);
        float acc = 0.f;
        #pragma unroll
        for (int i = 0; i < 8; i++) {
            float4 a = wp[i * 32 + lane];
            float4 v = vp[i * 32 + lane];
            acc += a.x * v.x + a.y * v.y + a.z * v.z + a.w * v.w;
        }
        #pragma unroll
        for (int o = 16; o; o >>= 1) acc += __shfl_down_sync(0xFFFFFFFFu, acc, o);
        if (lane == 0) {
            float lg = acc + outb[r];
            g_logits[r] = lg;
            rl[w * 4 + ri] = lg;
        }
    }
    __syncthreads();
    if (w == 0) {
        float x = rl[lane];
        float m = x;
        #pragma unroll
        for (int o = 16; o; o >>= 1) m = fmaxf(m, __shfl_xor_sync(0xFFFFFFFFu, m, o));
        float s = expf(x - m);
        #pragma unroll
        for (int o = 16; o; o >>= 1) s += __shfl_xor_sync(0xFFFFFFFFu, s, o);
        if (lane == 0) { g_pm[blockIdx.x] = m; g_ps[blockIdx.x] = s; }
    }
}

// ======= K3c: merge partials (L2-hot) -> write logp ========================
__global__ void k3c_logp(float* __restrict__ out) {
    const int NBK = 1000;
    int tid = threadIdx.x, lane = tid & 31;
    float m = g_pm[tid], s = g_ps[tid];
    for (int i = tid + 256; i < NBK; i += 256) {
        float m2 = g_pm[i], s2 = g_ps[i];
        float M = fmaxf(m, m2);
        s = s * expf(m - M) + s2 * expf(m2 - M);
        m = M;
    }
    #pragma unroll
    for (int o = 16; o; o >>= 1) {
        float m2 = __shfl_xor_sync(0xFFFFFFFFu, m, o);
        float s2 = __shfl_xor_sync(0xFFFFFFFFu, s, o);
        float M = fmaxf(m, m2);
        s = s * expf(m - M) + s2 * expf(m2 - M);
        m = M;
    }
    __shared__ float sm[8], ss[8];
    __shared__ float s_logZ;
    if (lane == 0) { sm[tid >> 5] = m; ss[tid >> 5] = s; }
    __syncthreads();
    if (tid == 0) {
        float M = sm[0], S = ss[0];
        #pragma unroll
        for (int i = 1; i < 8; i++) {
            float M2 = fmaxf(M, sm[i]);
            S = S * expf(M - M2) + ss[i] * expf(sm[i] - M2);
            M = M2;
        }
        s_logZ = M + logf(S);
    }
    __syncthreads();
    int idx = blockIdx.x * 256 + tid;
    out[idx] = g_logits[idx] - s_logZ;
}

extern "C" void kernel_launch(void* const* d_in, const int* in_sizes, int n_in,
                              void* d_out, int out_size) {
    const float* h    = (const float*)d_in[1];
    const float* enc  = (const float*)d_in[2];
    const float* Wihf = (const float*)d_in[6];
    const float* Whhf = (const float*)d_in[7];
    const float* bihf = (const float*)d_in[8];
    const float* bhhf = (const float*)d_in[9];
    const float* Wihb = (const float*)d_in[10];
    const float* Whhb = (const float*)d_in[11];
    const float* bihb = (const float*)d_in[12];
    const float* bhhb = (const float*)d_in[13];
    const float* outW = (const float*)d_in[14];
    const float* outb = (const float*)d_in[15];
    float* out = (float*)d_out;

    k1_reduce<<<1024, 256>>>(enc);                         // 256 MB stream
    k1b_finalize<<<256, 256>>>(h, out);                    // c, hT, attn fill
    k2_gru<<<1024, 128>>>(h, Wihf, Whhf, bihf, bhhf,
                          Wihb, Whhb, bihb, bhhb, out);    // h_new
    k3a_logits<<<1000, 256>>>(outW, outb, out);            // logits + partials
    k3c_logp<<<125, 256>>>(out);                           // logp
}

// round 11
// speedup vs baseline: 1.3331x; 1.1415x over previous
#include <cuda_runtime.h>
#include <math.h>

#define BB   32
#define LL   2048
#define HH   512
#define H2   1024
#define VV   32000

// ---- scratch ----
__device__ float g_part1[1024][H2];         // 4 MB block partials (32 per batch)
__device__ float g_cT[H2][BB];              // relu(mean) context, transposed
__device__ float g_hT[2][HH][BB];           // h transposed
__device__ float g_logits[VV];
__device__ float g_pm[1024];
__device__ float g_ps[1024];

// ======= K1: enc reduction, k3a register regime =============================
// 1024 blocks x 256 thr, <=64 regs (launch_bounds 256,4) -> 4 blocks/SM,
// 32 warps/SM. Thread t owns float4 column slot t; 8 row-loads in flight,
// only 2 float4 accumulators. No smem, no syncthreads.
__global__ void __launch_bounds__(256, 4) k1_reduce(const float* __restrict__ enc) {
    int b  = blockIdx.x >> 5;            // batch 0..31
    int ch = blockIdx.x & 31;            // 64-row chunk within batch
    int t  = threadIdx.x;                // float4 column slot
    const float4* base = (const float4*)enc + ((size_t)b * LL + ch * 64) * 256 + t;
    float4 a0 = make_float4(0.f, 0.f, 0.f, 0.f), a1 = a0;
    #pragma unroll 1
    for (int l = 0; l < 64; l += 8) {
        float4 v0 = base[(size_t)(l + 0) * 256];
        float4 v1 = base[(size_t)(l + 1) * 256];
        float4 v2 = base[(size_t)(l + 2) * 256];
        float4 v3 = base[(size_t)(l + 3) * 256];
        float4 v4 = base[(size_t)(l + 4) * 256];
        float4 v5 = base[(size_t)(l + 5) * 256];
        float4 v6 = base[(size_t)(l + 6) * 256];
        float4 v7 = base[(size_t)(l + 7) * 256];
        a0.x += (v0.x + v2.x) + (v4.x + v6.x);
        a0.y += (v0.y + v2.y) + (v4.y + v6.y);
        a0.z += (v0.z + v2.z) + (v4.z + v6.z);
        a0.w += (v0.w + v2.w) + (v4.w + v6.w);
        a1.x += (v1.x + v3.x) + (v5.x + v7.x);
        a1.y += (v1.y + v3.y) + (v5.y + v7.y);
        a1.z += (v1.z + v3.z) + (v5.z + v7.z);
        a1.w += (v1.w + v3.w) + (v5.w + v7.w);
    }
    float4 s;
    s.x = a0.x + a1.x;  s.y = a0.y + a1.y;
    s.z = a0.z + a1.z;  s.w = a0.w + a1.w;
    ((float4*)g_part1[blockIdx.x])[t] = s;
}

// ======= K1b: finalize c (relu/mean, transposed), transpose h, attn fill ===
__global__ void k1b_finalize(const float* __restrict__ h, float* __restrict__ out) {
    int idx = blockIdx.x * 256 + threadIdx.x;      // 0..65535
    out[VV + 2 * BB * HH + idx] = 1.0f / (float)LL;
    if (idx < BB * H2) {
        int b = idx >> 10, col = idx & (H2 - 1);
        float s = 0.f;
        #pragma unroll 8
        for (int ch = 0; ch < 32; ch++) s += g_part1[b * 32 + ch][col];
        s *= (1.0f / (float)LL);
        if (s < 0.f) s = 0.f;
        g_cT[col][b] = s;
        int dir = idx >> 14, bb = (idx >> 9) & 31, u = idx & (HH - 1);
        g_hT[dir][u][bb] = h[idx];
    }
}

// ======= K2: fused GRU, K-split x4 (4 warps per (dir,u)) ===================
__global__ void __launch_bounds__(128, 8) k2_gru(
        const float* __restrict__ h,
        const float* __restrict__ Wihf, const float* __restrict__ Whhf,
        const float* __restrict__ bihf, const float* __restrict__ bhhf,
        const float* __restrict__ Wihb, const float* __restrict__ Whhb,
        const float* __restrict__ bihb, const float* __restrict__ bhhb,
        float* __restrict__ out) {
    __shared__ float sp[3][4][32];
    int lane = threadIdx.x & 31;
    int w    = threadIdx.x >> 5;         // quarter 0..3
    int p    = blockIdx.x;               // 0..1023
    int dir  = p >> 9, u = p & (HH - 1);
    const float* Wih = dir ? Wihb : Wihf;
    const float* Whh = dir ? Whhb : Whhf;
    const float* bih = dir ? bihb : bihf;
    const float* bhh = dir ? bhhb : bhhf;

    float gr = 0.f, gz = 0.f, gin = 0.f, ghn = 0.f;
    {   // input-hidden quarter: cols [w*256, w*256+256)
        const float4* Wr = (const float4*)(Wih + (size_t)u * H2) + w * 64;
        const float4* Wz = (const float4*)(Wih + (size_t)(HH + u) * H2) + w * 64;
        const float4* Wn = (const float4*)(Wih + (size_t)(2 * HH + u) * H2) + w * 64;
        int kb = w * 256;
        #pragma unroll 8
        for (int k4 = 0; k4 < 64; k4++) {
            float c0 = g_cT[kb + k4 * 4 + 0][lane];
            float c1 = g_cT[kb + k4 * 4 + 1][lane];
            float c2 = g_cT[kb + k4 * 4 + 2][lane];
            float c3 = g_cT[kb + k4 * 4 + 3][lane];
            float4 wr = Wr[k4], wz = Wz[k4], wn = Wn[k4];
            gr  += c0 * wr.x + c1 * wr.y + c2 * wr.z + c3 * wr.w;
            gz  += c0 * wz.x + c1 * wz.y + c2 * wz.z + c3 * wz.w;
            gin += c0 * wn.x + c1 * wn.y + c2 * wn.z + c3 * wn.w;
        }
    }
    {   // hidden-hidden quarter: cols [w*128, w*128+128)
        const float4* Vr = (const float4*)(Whh + (size_t)u * HH) + w * 32;
        const float4* Vz = (const float4*)(Whh + (size_t)(HH + u) * HH) + w * 32;
        const float4* Vn = (const float4*)(Whh + (size_t)(2 * HH + u) * HH) + w * 32;
        int kb = w * 128;
        #pragma unroll 8
        for (int k4 = 0; k4 < 32; k4++) {
            float h0 = g_hT[dir][kb + k4 * 4 + 0][lane];
            float h1 = g_hT[dir][kb + k4 * 4 + 1][lane];
            float h2 = g_hT[dir][kb + k4 * 4 + 2][lane];
            float h3 = g_hT[dir][kb + k4 * 4 + 3][lane];
            float4 vr = Vr[k4], vz = Vz[k4], vn = Vn[k4];
            gr  += h0 * vr.x + h1 * vr.y + h2 * vr.z + h3 * vr.w;
            gz  += h0 * vz.x + h1 * vz.y + h2 * vz.z + h3 * vz.w;
            ghn += h0 * vn.x + h1 * vn.y + h2 * vn.z + h3 * vn.w;
        }
    }
    if (w) {
        sp[w - 1][0][lane] = gr;
        sp[w - 1][1][lane] = gz;
        sp[w - 1][2][lane] = gin;
        sp[w - 1][3][lane] = ghn;
    }
    __syncthreads();
    if (w == 0) {
        #pragma unroll
        for (int q = 0; q < 3; q++) {
            gr  += sp[q][0][lane];
            gz  += sp[q][1][lane];
            gin += sp[q][2][lane];
            ghn += sp[q][3][lane];
        }
        gr  += bih[u] + bhh[u];
        gz  += bih[HH + u] + bhh[HH + u];
        gin += bih[2 * HH + u];
        ghn += bhh[2 * HH + u];
        float r = 1.f / (1.f + expf(-gr));
        float z = 1.f / (1.f + expf(-gz));
        float n = tanhf(gin + r * ghn);
        float hold = h[dir * BB * HH + lane * HH + u];
        out[VV + dir * BB * HH + lane * HH + u] = (1.f - z) * n + z * hold;
    }
}

// ======= K3a: logits GEMV (proven 26.9us @ 5.0 TB/s; byte-identical) =======
__global__ void k3a_logits(const float* __restrict__ outW,
                           const float* __restrict__ outb,
                           const float* __restrict__ dout) {
    __shared__ float sv[H2];
    __shared__ float rl[32];
    int tid = threadIdx.x, lane = tid & 31, w = tid >> 5;
    for (int i = tid; i < H2; i += 256) {
        int dir = i >> 9, uu = i & (HH - 1);
        sv[i] = dout[VV + dir * BB * HH + 31 * HH + uu];
    }
    __syncthreads();
    int r0 = blockIdx.x * 32 + w * 4;
    const float4* vp = (const float4*)sv;
    #pragma unroll 1
    for (int ri = 0; ri < 4; ri++) {
        int r = r0 + ri;
        const float4* wp = (const float4*)(outW + (size_t)r * H2);
        float acc = 0.f;
        #pragma unroll
        for (int i = 0; i < 8; i++) {
            float4 a = wp[i * 32 + lane];
            float4 v = vp[i * 32 + lane];
            acc += a.x * v.x + a.y * v.y + a.z * v.z + a.w * v.w;
        }
        #pragma unroll
        for (int o = 16; o; o >>= 1) acc += __shfl_down_sync(0xFFFFFFFFu, acc, o);
        if (lane == 0) {
            float lg = acc + outb[r];
            g_logits[r] = lg;
            rl[w * 4 + ri] = lg;
        }
    }
    __syncthreads();
    if (w == 0) {
        float x = rl[lane];
        float m = x;
        #pragma unroll
        for (int o = 16; o; o >>= 1) m = fmaxf(m, __shfl_xor_sync(0xFFFFFFFFu, m, o));
        float s = expf(x - m);
        #pragma unroll
        for (int o = 16; o; o >>= 1) s += __shfl_xor_sync(0xFFFFFFFFu, s, o);
        if (lane == 0) { g_pm[blockIdx.x] = m; g_ps[blockIdx.x] = s; }
    }
}

// ======= K3c: merge partials (L2-hot) -> write logp ========================
__global__ void k3c_logp(float* __restrict__ out) {
    const int NBK = 1000;
    int tid = threadIdx.x, lane = tid & 31;
    float m = g_pm[tid], s = g_ps[tid];
    for (int i = tid + 256; i < NBK; i += 256) {
        float m2 = g_pm[i], s2 = g_ps[i];
        float M = fmaxf(m, m2);
        s = s * expf(m - M) + s2 * expf(m2 - M);
        m = M;
    }
    #pragma unroll
    for (int o = 16; o; o >>= 1) {
        float m2 = __shfl_xor_sync(0xFFFFFFFFu, m, o);
        float s2 = __shfl_xor_sync(0xFFFFFFFFu, s, o);
        float M = fmaxf(m, m2);
        s = s * expf(m - M) + s2 * expf(m2 - M);
        m = M;
    }
    __shared__ float sm[8], ss[8];
    __shared__ float s_logZ;
    if (lane == 0) { sm[tid >> 5] = m; ss[tid >> 5] = s; }
    __syncthreads();
    if (tid == 0) {
        float M = sm[0], S = ss[0];
        #pragma unroll
        for (int i = 1; i < 8; i++) {
            float M2 = fmaxf(M, sm[i]);
            S = S * expf(M - M2) + ss[i] * expf(sm[i] - M2);
            M = M2;
        }
        s_logZ = M + logf(S);
    }
    __syncthreads();
    int idx = blockIdx.x * 256 + tid;
    out[idx] = g_logits[idx] - s_logZ;
}

extern "C" void kernel_launch(void* const* d_in, const int* in_sizes, int n_in,
                              void* d_out, int out_size) {
    const float* h    = (const float*)d_in[1];
    const float* enc  = (const float*)d_in[2];
    const float* Wihf = (const float*)d_in[6];
    const float* Whhf = (const float*)d_in[7];
    const float* bihf = (const float*)d_in[8];
    const float* bhhf = (const float*)d_in[9];
    const float* Wihb = (const float*)d_in[10];
    const float* Whhb = (const float*)d_in[11];
    const float* bihb = (const float*)d_in[12];
    const float* bhhb = (const float*)d_in[13];
    const float* outW = (const float*)d_in[14];
    const float* outb = (const float*)d_in[15];
    float* out = (float*)d_out;

    k1_reduce<<<1024, 256>>>(enc);                         // 256 MB stream
    k1b_finalize<<<256, 256>>>(h, out);                    // c, hT, attn fill
    k2_gru<<<1024, 128>>>(h, Wihf, Whhf, bihf, bhhf,
                          Wihb, Whhb, bihb, bhhb, out);    // h_new
    k3a_logits<<<1000, 256>>>(outW, outb, out);            // logits + partials
    k3c_logp<<<125, 256>>>(out);                           // logp
}

// round 12
// speedup vs baseline: 1.3543x; 1.0159x over previous
#include <cuda_runtime.h>
#include <math.h>

#define BB   32
#define LL   2048
#define HH   512
#define H2   1024
#define VV   32000
#define NKB  592                 // k1 blocks = one full wave (4 x 148)

// ---- scratch ----
__device__ float g_seg0[NKB][H2];           // first-batch segment partials
__device__ float g_seg1[NKB][H2];           // second-batch segment partials
__device__ float g_cT[H2][BB];              // relu(mean) context, transposed
__device__ float g_hT[2][HH][BB];           // h transposed
__device__ float g_logits[VV];
__device__ float g_pm[1024];
__device__ float g_ps[1024];

// ---- self-resetting grid barrier for k2f ----
__device__ volatile unsigned g_genB = 0;
__device__ unsigned g_cntB = 0;

__device__ __forceinline__ void gbar(int n) {
    __syncthreads();
    if (threadIdx.x == 0) {
        unsigned g = g_genB;
        __threadfence();
        if (atomicAdd(&g_cntB, 1u) == (unsigned)(n - 1)) {
            g_cntB = 0;
            __threadfence();
            g_genB = g + 1;
        } else {
            while (g_genB == g) { }
        }
        __threadfence();
    }
    __syncthreads();
}

// ======= K1: enc reduction, 592 persistent blocks (single wave) ============
// Block i owns contiguous rows [i*65536/592, (i+1)*65536/592) (~111 rows),
// crossing at most one batch boundary. Thread t owns float4 column slot t.
// 8 loads in flight, 2 accumulators; <=64 regs -> 4 blocks/SM, 32 warps/SM.
__global__ void __launch_bounds__(256, 4) k1_reduce(const float* __restrict__ enc) {
    int i = blockIdx.x, t = threadIdx.x;
    int rs = (int)(((long long)i * 65536) / NKB);
    int re = (int)(((long long)(i + 1) * 65536) / NKB);
    const float4* base = (const float4*)enc + t;
    float4 a0 = make_float4(0.f, 0.f, 0.f, 0.f), a1 = a0;
    int r = rs, seg = 0;
    while (r < re) {
        int curb = r >> 11;
        int se = min(re, (curb + 1) << 11);
        for (; r + 8 <= se; r += 8) {
            float4 v0 = base[(size_t)(r + 0) * 256];
            float4 v1 = base[(size_t)(r + 1) * 256];
            float4 v2 = base[(size_t)(r + 2) * 256];
            float4 v3 = base[(size_t)(r + 3) * 256];
            float4 v4 = base[(size_t)(r + 4) * 256];
            float4 v5 = base[(size_t)(r + 5) * 256];
            float4 v6 = base[(size_t)(r + 6) * 256];
            float4 v7 = base[(size_t)(r + 7) * 256];
            a0.x += (v0.x + v2.x) + (v4.x + v6.x);
            a0.y += (v0.y + v2.y) + (v4.y + v6.y);
            a0.z += (v0.z + v2.z) + (v4.z + v6.z);
            a0.w += (v0.w + v2.w) + (v4.w + v6.w);
            a1.x += (v1.x + v3.x) + (v5.x + v7.x);
            a1.y += (v1.y + v3.y) + (v5.y + v7.y);
            a1.z += (v1.z + v3.z) + (v5.z + v7.z);
            a1.w += (v1.w + v3.w) + (v5.w + v7.w);
        }
        for (; r < se; r++) {
            float4 v = base[(size_t)r * 256];
            a0.x += v.x; a0.y += v.y; a0.z += v.z; a0.w += v.w;
        }
        float4 s;
        s.x = a0.x + a1.x;  s.y = a0.y + a1.y;
        s.z = a0.z + a1.z;  s.w = a0.w + a1.w;
        float4* dst = (float4*)(seg == 0 ? g_seg0[i] : g_seg1[i]);
        dst[t] = s;
        a0 = make_float4(0.f, 0.f, 0.f, 0.f);
        a1 = a0;
        seg++;
    }
}

// exact block index containing row r: max{i : floor(i*65536/NKB) <= r}
__device__ __forceinline__ int row_block(int r) {
    return (int)((((long long)(r + 1)) * NKB + 65535) / 65536) - 1;
}

// ======= K2f: finalize (cT/hT/attn) + grid barrier + fused GRU =============
// 1024 blocks x 128 thr, all co-resident (8 blocks/SM, <=64 regs).
__global__ void __launch_bounds__(128, 8) k2f(
        const float* __restrict__ h,
        const float* __restrict__ Wihf, const float* __restrict__ Whhf,
        const float* __restrict__ bihf, const float* __restrict__ bhhf,
        const float* __restrict__ Wihb, const float* __restrict__ Whhb,
        const float* __restrict__ bihb, const float* __restrict__ bhhb,
        float* __restrict__ out) {
    __shared__ float sp[3][4][32];
    int tid = threadIdx.x;
    int lane = tid & 31;
    int w    = tid >> 5;                 // 0..3
    int bid  = blockIdx.x;               // 0..1023

    // ---- Phase A: one element per thread over 131072 slots ----
    {
        int idx = bid * 128 + tid;       // 0..131071
        if (idx < BB * H2) {
            int b = idx >> 10, col = idx & (H2 - 1);
            int lo = row_block(b << 11);
            int hi = row_block(((b + 1) << 11) - 1);
            float s = 0.f;
            for (int i = lo; i <= hi; i++) {
                int si = (int)(((long long)i * 65536) / NKB);
                s += ((si >> 11) == b) ? g_seg0[i][col] : g_seg1[i][col];
            }
            s *= (1.0f / (float)LL);
            if (s < 0.f) s = 0.f;
            g_cT[col][b] = s;
        } else if (idx < 2 * BB * H2) {
            int j = idx - BB * H2;       // over [2][32][512]
            int dir = j >> 14, bb = (j >> 9) & 31, u = j & (HH - 1);
            g_hT[dir][u][bb] = h[j];
        } else {
            out[VV + 2 * BB * HH + (idx - 2 * BB * H2)] = 1.0f / (float)LL;
        }
    }
    gbar(1024);

    // ---- Phase B: GRU, K-split x4 (4 warps per (dir,u)) ----
    int p   = bid;                       // 0..1023
    int dir = p >> 9, u = p & (HH - 1);
    const float* Wih = dir ? Wihb : Wihf;
    const float* Whh = dir ? Whhb : Whhf;
    const float* bih = dir ? bihb : bihf;
    const float* bhh = dir ? bhhb : bhhf;

    float gr = 0.f, gz = 0.f, gin = 0.f, ghn = 0.f;
    {   // input-hidden quarter: cols [w*256, w*256+256)
        const float4* Wr = (const float4*)(Wih + (size_t)u * H2) + w * 64;
        const float4* Wz = (const float4*)(Wih + (size_t)(HH + u) * H2) + w * 64;
        const float4* Wn = (const float4*)(Wih + (size_t)(2 * HH + u) * H2) + w * 64;
        int kb = w * 256;
        #pragma unroll 8
        for (int k4 = 0; k4 < 64; k4++) {
            float c0 = g_cT[kb + k4 * 4 + 0][lane];
            float c1 = g_cT[kb + k4 * 4 + 1][lane];
            float c2 = g_cT[kb + k4 * 4 + 2][lane];
            float c3 = g_cT[kb + k4 * 4 + 3][lane];
            float4 wr = Wr[k4], wz = Wz[k4], wn = Wn[k4];
            gr  += c0 * wr.x + c1 * wr.y + c2 * wr.z + c3 * wr.w;
            gz  += c0 * wz.x + c1 * wz.y + c2 * wz.z + c3 * wz.w;
            gin += c0 * wn.x + c1 * wn.y + c2 * wn.z + c3 * wn.w;
        }
    }
    {   // hidden-hidden quarter: cols [w*128, w*128+128)
        const float4* Vr = (const float4*)(Whh + (size_t)u * HH) + w * 32;
        const float4* Vz = (const float4*)(Whh + (size_t)(HH + u) * HH) + w * 32;
        const float4* Vn = (const float4*)(Whh + (size_t)(2 * HH + u) * HH) + w * 32;
        int kb = w * 128;
        #pragma unroll 8
        for (int k4 = 0; k4 < 32; k4++) {
            float h0 = g_hT[dir][kb + k4 * 4 + 0][lane];
            float h1 = g_hT[dir][kb + k4 * 4 + 1][lane];
            float h2 = g_hT[dir][kb + k4 * 4 + 2][lane];
            float h3 = g_hT[dir][kb + k4 * 4 + 3][lane];
            float4 vr = Vr[k4], vz = Vz[k4], vn = Vn[k4];
            gr  += h0 * vr.x + h1 * vr.y + h2 * vr.z + h3 * vr.w;
            gz  += h0 * vz.x + h1 * vz.y + h2 * vz.z + h3 * vz.w;
            ghn += h0 * vn.x + h1 * vn.y + h2 * vn.z + h3 * vn.w;
        }
    }
    if (w) {
        sp[w - 1][0][lane] = gr;
        sp[w - 1][1][lane] = gz;
        sp[w - 1][2][lane] = gin;
        sp[w - 1][3][lane] = ghn;
    }
    __syncthreads();
    if (w == 0) {
        #pragma unroll
        for (int q = 0; q < 3; q++) {
            gr  += sp[q][0][lane];
            gz  += sp[q][1][lane];
            gin += sp[q][2][lane];
            ghn += sp[q][3][lane];
        }
        gr  += bih[u] + bhh[u];
        gz  += bih[HH + u] + bhh[HH + u];
        gin += bih[2 * HH + u];
        ghn += bhh[2 * HH + u];
        float r = 1.f / (1.f + expf(-gr));
        float z = 1.f / (1.f + expf(-gz));
        float n = tanhf(gin + r * ghn);
        float hold = h[dir * BB * HH + lane * HH + u];
        out[VV + dir * BB * HH + lane * HH + u] = (1.f - z) * n + z * hold;
    }
}

// ======= K3a: logits GEMV (proven ~27us @ 5.0 TB/s; byte-identical) ========
__global__ void k3a_logits(const float* __restrict__ outW,
                           const float* __restrict__ outb,
                           const float* __restrict__ dout) {
    __shared__ float sv[H2];
    __shared__ float rl[32];
    int tid = threadIdx.x, lane = tid & 31, w = tid >> 5;
    for (int i = tid; i < H2; i += 256) {
        int dir = i >> 9, uu = i & (HH - 1);
        sv[i] = dout[VV + dir * BB * HH + 31 * HH + uu];
    }
    __syncthreads();
    int r0 = blockIdx.x * 32 + w * 4;
    const float4* vp = (const float4*)sv;
    #pragma unroll 1
    for (int ri = 0; ri < 4; ri++) {
        int r = r0 + ri;
        const float4* wp = (const float4*)(outW + (size_t)r * H2);
        float acc = 0.f;
        #pragma unroll
        for (int i = 0; i < 8; i++) {
            float4 a = wp[i * 32 + lane];
            float4 v = vp[i * 32 + lane];
            acc += a.x * v.x + a.y * v.y + a.z * v.z + a.w * v.w;
        }
        #pragma unroll
        for (int o = 16; o; o >>= 1) acc += __shfl_down_sync(0xFFFFFFFFu, acc, o);
        if (lane == 0) {
            float lg = acc + outb[r];
            g_logits[r] = lg;
            rl[w * 4 + ri] = lg;
        }
    }
    __syncthreads();
    if (w == 0) {
        float x = rl[lane];
        float m = x;
        #pragma unroll
        for (int o = 16; o; o >>= 1) m = fmaxf(m, __shfl_xor_sync(0xFFFFFFFFu, m, o));
        float s = expf(x - m);
        #pragma unroll
        for (int o = 16; o; o >>= 1) s += __shfl_xor_sync(0xFFFFFFFFu, s, o);
        if (lane == 0) { g_pm[blockIdx.x] = m; g_ps[blockIdx.x] = s; }
    }
}

// ======= K3c: merge partials (L2-hot) -> write logp ========================
__global__ void k3c_logp(float* __restrict__ out) {
    const int NBK = 1000;
    int tid = threadIdx.x, lane = tid & 31;
    float m = g_pm[tid], s = g_ps[tid];
    for (int i = tid + 256; i < NBK; i += 256) {
        float m2 = g_pm[i], s2 = g_ps[i];
        float M = fmaxf(m, m2);
        s = s * expf(m - M) + s2 * expf(m2 - M);
        m = M;
    }
    #pragma unroll
    for (int o = 16; o; o >>= 1) {
        float m2 = __shfl_xor_sync(0xFFFFFFFFu, m, o);
        float s2 = __shfl_xor_sync(0xFFFFFFFFu, s, o);
        float M = fmaxf(m, m2);
        s = s * expf(m - M) + s2 * expf(m2 - M);
        m = M;
    }
    __shared__ float sm[8], ss[8];
    __shared__ float s_logZ;
    if (lane == 0) { sm[tid >> 5] = m; ss[tid >> 5] = s; }
    __syncthreads();
    if (tid == 0) {
        float M = sm[0], S = ss[0];
        #pragma unroll
        for (int i = 1; i < 8; i++) {
            float M2 = fmaxf(M, sm[i]);
            S = S * expf(M - M2) + ss[i] * expf(sm[i] - M2);
            M = M2;
        }
        s_logZ = M + logf(S);
    }
    __syncthreads();
    int idx = blockIdx.x * 256 + tid;
    out[idx] = g_logits[idx] - s_logZ;
}

extern "C" void kernel_launch(void* const* d_in, const int* in_sizes, int n_in,
                              void* d_out, int out_size) {
    const float* h    = (const float*)d_in[1];
    const float* enc  = (const float*)d_in[2];
    const float* Wihf = (const float*)d_in[6];
    const float* Whhf = (const float*)d_in[7];
    const float* bihf = (const float*)d_in[8];
    const float* bhhf = (const float*)d_in[9];
    const float* Wihb = (const float*)d_in[10];
    const float* Whhb = (const float*)d_in[11];
    const float* bihb = (const float*)d_in[12];
    const float* bhhb = (const float*)d_in[13];
    const float* outW = (const float*)d_in[14];
    const float* outb = (const float*)d_in[15];
    float* out = (float*)d_out;

    k1_reduce<<<NKB, 256>>>(enc);                          // 256 MB, one wave
    k2f<<<1024, 128>>>(h, Wihf, Whhf, bihf, bhhf,
                       Wihb, Whhb, bihb, bhhb, out);       // finalize + GRU
    k3a_logits<<<1000, 256>>>(outW, outb, out);            // logits + partials
    k3c_logp<<<125, 256>>>(out);                           // logp
}